// round 15
// baseline (speedup 1.0000x reference)
#include <cuda_runtime.h>
#include <cuda_fp16.h>

#define Nn 22
#define Fd 192
#define NB4 4
#define MR 96
#define THREADS 768

typedef unsigned int u32;
typedef unsigned short u16;

// ---- SMEM layout (bytes) ----
#define OFF_ADJ 0                 // 484 f
#define OFF_AVS 1952              // 1152 f
#define OFF_WS  6560              // 4 x 550 f (ev scratch)
#define OFF_ATT 15360             // 4 x 32 rows x 80B fp16 att (zero padded)
#define OFF_AX  25600             // x fp16: 96 rows x 400B
#define ASTR    400
#define OFF_AH  64000             // hc/who fp16: 98 rows x 400B (rows 88..97 zeroed)
#define OFF_WHS 103200            // Wh fp16: 98 rows x 400B (rows 96..97 zeroed)
#define OFF_B   142400            // 3-stage: 3 x (192 rows x 64 fp16, stride 144)
#define BSTR    144
#define BBUF    27648
#define SMEM_TOTAL 225344

// ---- device-global fp16 weights (sanctioned scratch) ----
static __device__ __half g_w12t[384*192];    // [n][k], n<192: W1, else W2
static __device__ __half g_wot[192*384];     // Wo^T [n][k]

// ---- helpers ----
__device__ __forceinline__ u32 smem_u32(const void* p){
    u32 a;
    asm("{ .reg .u64 t; cvta.to.shared.u64 t, %1; cvt.u32.u64 %0, t; }" : "=r"(a) : "l"(p));
    return a;
}
__device__ __forceinline__ float elu1(float v){ return (v > 0.0f) ? v : (__expf(v) - 1.0f); }

#define CPA16(sa, g) asm volatile("cp.async.cg.shared.global [%0], [%1], 16;" :: "r"((u32)(sa)), "l"(g) : "memory")
#define CPC()  asm volatile("cp.async.commit_group;" ::: "memory")
#define CPW1() asm volatile("cp.async.wait_group 1;" ::: "memory")
#define CPW0() asm volatile("cp.async.wait_group 0;" ::: "memory")

__device__ __forceinline__ void mma_f16(float* c, const u32* a, u32 b0, u32 b1){
    asm volatile("mma.sync.aligned.m16n8k16.row.col.f32.f16.f16.f32 "
        "{%0,%1,%2,%3}, {%4,%5,%6,%7}, {%8,%9}, {%0,%1,%2,%3};"
        : "+f"(c[0]),"+f"(c[1]),"+f"(c[2]),"+f"(c[3])
        : "r"(a[0]),"r"(a[1]),"r"(a[2]),"r"(a[3]),"r"(b0),"r"(b1));
}
__device__ __forceinline__ void ldsm4(u32 a, u32* r){
    asm volatile("ldmatrix.sync.aligned.m8n8.x4.shared.b16 {%0,%1,%2,%3}, [%4];"
        : "=r"(r[0]),"=r"(r[1]),"=r"(r[2]),"=r"(r[3]) : "r"(a));
}
__device__ __forceinline__ void ldsm2(u32 a, u32* r){
    asm volatile("ldmatrix.sync.aligned.m8n8.x2.shared.b16 {%0,%1}, [%2];"
        : "=r"(r[0]),"=r"(r[1]) : "r"(a));
}
__device__ __forceinline__ void ldsm2t(u32 a, u32* r){
    asm volatile("ldmatrix.sync.aligned.m8n8.x2.trans.shared.b16 {%0,%1}, [%2];"
        : "=r"(r[0]),"=r"(r[1]) : "r"(a));
}

// softmax over 22 nodes; lane i handles row i; writes fp16 att row (stride 80B)
__device__ __forceinline__ void warp_softmax_h16(const float* __restrict__ ev, const float* __restrict__ adjs,
                                                 char* __restrict__ attb, int lane)
{
    if (lane < Nn) {
        int i = lane;
        float esrc = ev[i];
        float vals[Nn];
        float mx = -1e30f;
#pragma unroll
        for (int j = 0; j < Nn; j++) {
            if (adjs[i * Nn + j] != 0.0f) {
                float v = esrc + ev[Nn + j];
                v = (v > 0.0f) ? v : 0.2f * v;
                vals[j] = v;
                mx = fmaxf(mx, v);
            } else vals[j] = -1e30f;
        }
        float ssum = 0.0f;
#pragma unroll
        for (int j = 0; j < Nn; j++) {
            float e = (vals[j] > -1e29f) ? __expf(vals[j] - mx) : 0.0f;
            vals[j] = e; ssum += e;
        }
        float inv = 1.0f / ssum;
#pragma unroll
        for (int j = 0; j < Nn; j++) {
            __half hv = __float2half_rn(vals[j] * inv);
            *(u16*)(attb + i * 80 + j * 2) = *(u16*)&hv;
        }
    }
}

// e-dot: fp16 row (stride 400B), fp32 a-vector
__device__ __forceinline__ float edot192(const char* rowp, const float* av, int lane)
{
    float s = 0.0f;
#pragma unroll
    for (int j = 0; j < 3; j++) {
        u32 v = *(const u32*)(rowp + (lane + 32 * j) * 4);
        float2 f = __half22float2(*(__half2*)&v);
        float2 a = *(const float2*)(av + (lane + 32 * j) * 2);
        s += f.x * a.x + f.y * a.y;
    }
#pragma unroll
    for (int o = 16; o; o >>= 1) s += __shfl_xor_sync(0xffffffffu, s, o);
    return s;
}

// stream one B chunk: 192 n-rows x 64 k fp16 (1536 x 16B ops)
__device__ __forceinline__ void issue_b(u32 dst, const __half* g, int tid, int rs)
{
#pragma unroll
    for (int q = 0; q < 2; q++) {
        int lin = tid + THREADS * q;
        int row = lin >> 3, piece = lin & 7;
        CPA16(dst + row * BSTR + piece * 16, g + row * rs + piece * 8);
    }
}

// 3-stage GEMM over 3 k64-chunks. REQUIRES chunks 0,1 already committed.
// Issues own chunk2 at kc=0, and NEXT gemm's chunks 0,1 at kc=2 (if nextg).
// Warp tile 32x24: acc[2][3][4].
__device__ __forceinline__ void gemm3p(u32 sb, float acc[2][3][4], u32 aoff,
                                       const __half* b0g, int rs,
                                       const __half* nextg, int nrs,
                                       int tid, int wm, int wn, int lane)
{
    const u32 laneA = (u32)((lane & 15) * ASTR + (lane >> 4) * 16);
    const u32 laneB = (u32)((lane & 7) * BSTR + ((lane >> 3) & 1) * 16);
    const u32 Abase = sb + aoff + wm * 32 * ASTR + laneA;
    const u32 Bbase = sb + OFF_B + wn * 24 * BSTR + laneB;

#pragma unroll
    for (int kc = 0; kc < 3; kc++) {
        if (kc < 2) { CPW1(); } else { CPW0(); }
        __syncthreads();
        if (kc == 0) {
            issue_b(sb + OFF_B + 2 * BBUF, b0g + 128, tid, rs);
            CPC();
        }
        if (kc == 2 && nextg) {
            issue_b(sb + OFF_B, nextg, tid, nrs);
            CPC();
            issue_b(sb + OFF_B + BBUF, nextg + 64, tid, nrs);
            CPC();
        }
        const u32 Ah = Abase + kc * 128;
        const u32 Bh = Bbase + kc * BBUF;
#pragma unroll
        for (int s = 0; s < 4; s++) {
            u32 ah[2][4], bh[3][2];
#pragma unroll
            for (int mt = 0; mt < 2; mt++)
                ldsm4(Ah + mt * 16 * ASTR + s * 32, ah[mt]);
#pragma unroll
            for (int t = 0; t < 3; t++)
                ldsm2(Bh + t * 8 * BSTR + s * 32, bh[t]);
#pragma unroll
            for (int mt = 0; mt < 2; mt++)
#pragma unroll
                for (int t = 0; t < 3; t++)
                    mma_f16(acc[mt][t], ah[mt], bh[t][0], bh[t][1]);
        }
    }
}

// ================= prep =================
__global__ void k_prep(const float* __restrict__ W1, const float* __restrict__ W2,
                       const float* __restrict__ Wo)
{
    int idx = blockIdx.x * blockDim.x + threadIdx.x;
    if (idx < 384 * 192) {
        int n = idx / 192, k = idx % 192;
        float v = (n < 192) ? W1[k * 192 + n] : W2[k * 192 + (n - 192)];
        g_w12t[idx] = __float2half_rn(v);
    } else if (idx < 2 * 384 * 192) {
        int j = idx - 384 * 192;
        int n = j / 384, k = j % 384;
        g_wot[j] = __float2half_rn(Wo[k * 192 + n]);
    }
}

// ================= fused kernel =================
__global__ __launch_bounds__(THREADS, 1)
void k_fused(const float* __restrict__ x, const float* __restrict__ adj,
             const float* __restrict__ a1, const float* __restrict__ a2,
             const float* __restrict__ ao, float* __restrict__ out, int nbatch)
{
    extern __shared__ char smc[];
    float* smf = (float*)smc;
    const u32 sb = smem_u32(smc);
    const int tid = threadIdx.x, wid = tid >> 5, lane = tid & 31;
    const int l4 = lane >> 2, lq = lane & 3;
    const int wm = wid >> 3, wn = wid & 7;       // GEMM roles: 3M x 8N
    const int wb = wid / 6, wS = wid % 6;        // attention roles: 4 batches x 6 slices
    const int b0 = blockIdx.x * NB4;
    const int nb = min(NB4, nbatch - b0);
    const int nrows = nb * Nn;
    const long long row0 = (long long)b0 * Nn;

    float* adjs = smf + OFF_ADJ / 4;
    float* avs  = smf + OFF_AVS / 4;

    // prefetch GEMM1-h0 chunks 0,1 before anything else
    issue_b(sb + OFF_B, g_w12t, tid, 192);
    CPC();
    issue_b(sb + OFF_B + BBUF, g_w12t + 64, tid, 192);
    CPC();

    for (int i = tid; i < Nn * Nn; i += THREADS) adjs[i] = adj[i];
    for (int i = tid; i < 1152; i += THREADS)
        avs[i] = (i < 384) ? a1[i] : (i < 768 ? a2[i - 384] : ao[i - 768]);

    // zero: att pads, whs rows 96..97, AH rows 88..97 (finite for ldsm2t over-reads)
    for (int i = tid; i < 2560; i += THREADS) ((u32*)(smc + OFF_ATT))[i] = 0;
    for (int i = tid; i < 200; i += THREADS)  ((u32*)(smc + OFF_WHS + 96 * ASTR))[i] = 0;
    for (int i = tid; i < 1000; i += THREADS) ((u32*)(smc + OFF_AH + 88 * ASTR))[i] = 0;

    // AX = fp16(x): 96 rows x 192 (pad rows zeroed) — written ONCE
    for (int idx = tid; idx < MR * 96; idx += THREADS) {
        int r = idx / 96, kp = idx % 96;
        float2 v = make_float2(0.f, 0.f);
        if (r < nrows) v = *(const float2*)(x + (row0 + r) * Fd + kp * 2);
        __half2 h2 = __float22half2_rn(v);
        *(u32*)(smc + OFF_AX + r * ASTR + kp * 4) = *(u32*)&h2;
    }

    float acc2[2][3][4];
#pragma unroll
    for (int mt = 0; mt < 2; mt++)
#pragma unroll
        for (int nt = 0; nt < 3; nt++)
#pragma unroll
            for (int p = 0; p < 4; p++) acc2[mt][nt][p] = 0.0f;

    for (int h = 0; h < 2; h++) {
        // ---- GEMM1 head h: Wh = x @ Wh_h -> whs (fp16); prefetch GEMM2-h ----
        {
            float acc[2][3][4];
#pragma unroll
            for (int mt = 0; mt < 2; mt++)
#pragma unroll
                for (int nt = 0; nt < 3; nt++)
#pragma unroll
                    for (int p = 0; p < 4; p++) acc[mt][nt][p] = 0.0f;

            gemm3p(sb, acc, OFF_AX, g_w12t + h * 192 * 192, 192,
                   g_wot + h * 192, 384, tid, wm, wn, lane);

            // whs epilogue: warp-exclusive cells; no pre-barrier needed
#pragma unroll
            for (int mt = 0; mt < 2; mt++)
#pragma unroll
                for (int nt = 0; nt < 3; nt++) {
                    int r = wm * 32 + mt * 16 + l4, c = wn * 24 + nt * 8 + lq * 2;
                    __half2 p0 = __floats2half2_rn(acc[mt][nt][0], acc[mt][nt][1]);
                    __half2 p1 = __floats2half2_rn(acc[mt][nt][2], acc[mt][nt][3]);
                    *(u32*)(smc + OFF_WHS + r * ASTR + c * 2)       = *(u32*)&p0;
                    *(u32*)(smc + OFF_WHS + (r + 8) * ASTR + c * 2) = *(u32*)&p1;
                }
        }
        __syncthreads();   // whs visible

        // ---- e-dots + softmax (fp16 att) ----
        float* ev = smf + OFF_WS / 4 + wb * 550;
        {
            const float* avh = avs + h * 384;
            for (int d = wS; d < 44; d += 6) {
                int sd = d / Nn, i = d - sd * Nn;
                float s = edot192(smc + OFF_WHS + (wb * Nn + i) * ASTR, avh + sd * 192, lane);
                if (lane == 0) ev[sd * Nn + i] = s;
            }
        }
        __syncthreads();
        if (wS == 0) warp_softmax_h16(ev, adjs, smc + OFF_ATT + wb * 2560, lane);
        __syncthreads();

        // ---- hc = elu(att @ Wh) via MMA -> AH (fp16); 32 cols per warp ----
        {
            const u32 attb = sb + OFF_ATT + wb * 2560;
            const u32 whb  = sb + OFF_WHS + (wb * Nn) * ASTR;
            float aw[2][4][4];
#pragma unroll
            for (int mt = 0; mt < 2; mt++)
#pragma unroll
                for (int nt = 0; nt < 4; nt++)
#pragma unroll
                    for (int p = 0; p < 4; p++) aw[mt][nt][p] = 0.0f;

            u32 afr[2][2][4];
#pragma unroll
            for (int mt = 0; mt < 2; mt++)
#pragma unroll
                for (int ks = 0; ks < 2; ks++)
                    ldsm4(attb + (mt * 16 + (lane & 15)) * 80 + (lane >> 4) * 16 + ks * 32,
                          afr[mt][ks]);
#pragma unroll
            for (int nt = 0; nt < 4; nt++) {
                int n0 = wS * 32 + nt * 8;
                u32 bfr[2][2];
#pragma unroll
                for (int ks = 0; ks < 2; ks++)
                    ldsm2t(whb + (ks * 16 + (lane & 15)) * ASTR + n0 * 2, bfr[ks]);
#pragma unroll
                for (int mt = 0; mt < 2; mt++)
#pragma unroll
                    for (int ks = 0; ks < 2; ks++)
                        mma_f16(aw[mt][nt], afr[mt][ks], bfr[ks][0], bfr[ks][1]);
            }
#pragma unroll
            for (int mt = 0; mt < 2; mt++)
#pragma unroll
                for (int nt = 0; nt < 4; nt++) {
                    int r0 = mt * 16 + l4, r1 = r0 + 8;
                    int c = wS * 32 + nt * 8 + lq * 2;
                    if (r0 < Nn) {
                        __half2 p0 = __floats2half2_rn(elu1(aw[mt][nt][0]), elu1(aw[mt][nt][1]));
                        *(u32*)(smc + OFF_AH + (wb * Nn + r0) * ASTR + c * 2) = *(u32*)&p0;
                    }
                    if (r1 < Nn) {
                        __half2 p1 = __floats2half2_rn(elu1(aw[mt][nt][2]), elu1(aw[mt][nt][3]));
                        *(u32*)(smc + OFF_AH + (wb * Nn + r1) * ASTR + c * 2) = *(u32*)&p1;
                    }
                }
        }
        // gemm3p's kc=0 barrier publishes AH before A-reads

        // ---- GEMM2 partial: k-half h (A = AH); prefetch next gemm ----
        gemm3p(sb, acc2, OFF_AH, g_wot + h * 192, 384,
               (h == 0) ? (g_w12t + 192 * 192) : (const __half*)0, 192,
               tid, wm, wn, lane);
    }

    // ---- epilogue: acc2 -> who (fp16, AH plane) ----
    __syncthreads();
#pragma unroll
    for (int mt = 0; mt < 2; mt++)
#pragma unroll
        for (int nt = 0; nt < 3; nt++) {
            int r = wm * 32 + mt * 16 + l4, c = wn * 24 + nt * 8 + lq * 2;
            __half2 p0 = __floats2half2_rn(acc2[mt][nt][0], acc2[mt][nt][1]);
            __half2 p1 = __floats2half2_rn(acc2[mt][nt][2], acc2[mt][nt][3]);
            *(u32*)(smc + OFF_AH + r * ASTR + c * 2)       = *(u32*)&p0;
            *(u32*)(smc + OFF_AH + (r + 8) * ASTR + c * 2) = *(u32*)&p1;
        }
    __syncthreads();

    // ---- output attention: e-dots + fp16 softmax + MMA + elu + residual ----
    float* ev = smf + OFF_WS / 4 + wb * 550;
    {
        const float* avo = avs + 768;
        for (int d = wS; d < 44; d += 6) {
            int sd = d / Nn, i = d - sd * Nn;
            float s = edot192(smc + OFF_AH + (wb * Nn + i) * ASTR, avo + sd * 192, lane);
            if (lane == 0) ev[sd * Nn + i] = s;
        }
    }
    __syncthreads();
    if (wS == 0) warp_softmax_h16(ev, adjs, smc + OFF_ATT + wb * 2560, lane);
    __syncthreads();
    {
        const u32 attb = sb + OFF_ATT + wb * 2560;
        const u32 whb  = sb + OFF_AH + (wb * Nn) * ASTR;
        float aw[2][4][4];
#pragma unroll
        for (int mt = 0; mt < 2; mt++)
#pragma unroll
            for (int nt = 0; nt < 4; nt++)
#pragma unroll
                for (int p = 0; p < 4; p++) aw[mt][nt][p] = 0.0f;

        u32 afr[2][2][4];
#pragma unroll
        for (int mt = 0; mt < 2; mt++)
#pragma unroll
            for (int ks = 0; ks < 2; ks++)
                ldsm4(attb + (mt * 16 + (lane & 15)) * 80 + (lane >> 4) * 16 + ks * 32,
                      afr[mt][ks]);
#pragma unroll
        for (int nt = 0; nt < 4; nt++) {
            int n0 = wS * 32 + nt * 8;
            u32 bfr[2][2];
#pragma unroll
            for (int ks = 0; ks < 2; ks++)
                ldsm2t(whb + (ks * 16 + (lane & 15)) * ASTR + n0 * 2, bfr[ks]);
#pragma unroll
            for (int mt = 0; mt < 2; mt++)
#pragma unroll
                for (int ks = 0; ks < 2; ks++)
                    mma_f16(aw[mt][nt], afr[mt][ks], bfr[ks][0], bfr[ks][1]);
        }
        if (wb < nb) {
#pragma unroll
            for (int mt = 0; mt < 2; mt++)
#pragma unroll
                for (int nt = 0; nt < 4; nt++) {
                    int r0 = mt * 16 + l4, r1 = r0 + 8;
                    int c = wS * 32 + nt * 8 + lq * 2;
                    if (r0 < Nn) {
                        long long gi = (row0 + wb * Nn + r0) * Fd + c;
                        float2 xr = *(const float2*)(x + gi);
                        float2 o;
                        o.x = elu1(aw[mt][nt][0]) + xr.x;
                        o.y = elu1(aw[mt][nt][1]) + xr.y;
                        *(float2*)(out + gi) = o;
                    }
                    if (r1 < Nn) {
                        long long gi = (row0 + wb * Nn + r1) * Fd + c;
                        float2 xr = *(const float2*)(x + gi);
                        float2 o;
                        o.x = elu1(aw[mt][nt][2]) + xr.x;
                        o.y = elu1(aw[mt][nt][3]) + xr.y;
                        *(float2*)(out + gi) = o;
                    }
                }
        }
    }
}

extern "C" void kernel_launch(void* const* d_in, const int* in_sizes, int n_in,
                              void* d_out, int out_size)
{
    const float* x   = (const float*)d_in[0];
    const float* adj = (const float*)d_in[1];
    const float* W1  = (const float*)d_in[2];
    const float* a1  = (const float*)d_in[3];
    const float* W2  = (const float*)d_in[4];
    const float* a2  = (const float*)d_in[5];
    const float* Wo  = (const float*)d_in[6];
    const float* ao  = (const float*)d_in[7];
    float* out = (float*)d_out;

    int nbatch = in_sizes[0] / (Nn * Fd);
    int ctas = (nbatch + NB4 - 1) / NB4;

    cudaFuncSetAttribute(k_fused, cudaFuncAttributeMaxDynamicSharedMemorySize, SMEM_TOTAL);

    k_prep<<<(2 * 384 * 192 + 255) / 256, 256>>>(W1, W2, Wo);
    k_fused<<<ctas, THREADS, SMEM_TOTAL>>>(x, adj, a1, a2, ao, out, nbatch);
}

// round 16
// speedup vs baseline: 1.4529x; 1.4529x over previous
#include <cuda_runtime.h>
#include <cuda_fp16.h>

#define Nn 22
#define Fd 192
#define NB4 4
#define MR 96
#define THREADS 512

typedef unsigned int u32;
typedef unsigned short u16;

// ---- SMEM layout (bytes) ----
#define OFF_ADJ 0                 // 484 f
#define OFF_WS  1952              // 4 x 64 f ev (esrc[22], edst[22])
#define OFF_ATT 2976              // 4 x 32 rows x 80B fp16 att (zero padded)
#define OFF_AX  13216             // x fp16: 96 rows x 400B
#define ASTR    400
#define OFF_AH  51616             // hc0 / who fp16: 98 rows x 400B (rows 88..97 zeroed)
#define OFF_WHS 90816             // Wh / hc1 fp16: 98 rows x 400B (rows 96..97 zeroed)
#define OFF_B   130016            // 3-stage: 3 x (200 rows x 64 fp16, stride 144)
#define BSTR    144
#define BROWS   200
#define BBUF    28800
#define SMEM_TOTAL 216416

// ---- device-global fp16 weights with e-rows (sanctioned scratch) ----
// per head: 200 rows x 192 (rows 0..191 = W^T, 192/193 = W@a_src/dst, 194.. = 0)
static __device__ __half g_w12t[2*200*192];
// 200 rows x 384 (rows 0..191 = Wo^T, 192/193 = Wo@ao_src/dst, 194.. = 0)
static __device__ __half g_wot[200*384];

// ---- helpers ----
__device__ __forceinline__ u32 smem_u32(const void* p){
    u32 a;
    asm("{ .reg .u64 t; cvta.to.shared.u64 t, %1; cvt.u32.u64 %0, t; }" : "=r"(a) : "l"(p));
    return a;
}
__device__ __forceinline__ float elu1(float v){ return (v > 0.0f) ? v : (__expf(v) - 1.0f); }

#define CPA16(sa, g) asm volatile("cp.async.cg.shared.global [%0], [%1], 16;" :: "r"((u32)(sa)), "l"(g) : "memory")
#define CPC()  asm volatile("cp.async.commit_group;" ::: "memory")
#define CPW1() asm volatile("cp.async.wait_group 1;" ::: "memory")
#define CPW0() asm volatile("cp.async.wait_group 0;" ::: "memory")

__device__ __forceinline__ void mma_f16(float* c, const u32* a, u32 b0, u32 b1){
    asm volatile("mma.sync.aligned.m16n8k16.row.col.f32.f16.f16.f32 "
        "{%0,%1,%2,%3}, {%4,%5,%6,%7}, {%8,%9}, {%0,%1,%2,%3};"
        : "+f"(c[0]),"+f"(c[1]),"+f"(c[2]),"+f"(c[3])
        : "r"(a[0]),"r"(a[1]),"r"(a[2]),"r"(a[3]),"r"(b0),"r"(b1));
}
__device__ __forceinline__ void ldsm4(u32 a, u32* r){
    asm volatile("ldmatrix.sync.aligned.m8n8.x4.shared.b16 {%0,%1,%2,%3}, [%4];"
        : "=r"(r[0]),"=r"(r[1]),"=r"(r[2]),"=r"(r[3]) : "r"(a));
}
__device__ __forceinline__ void ldsm2(u32 a, u32* r){
    asm volatile("ldmatrix.sync.aligned.m8n8.x2.shared.b16 {%0,%1}, [%2];"
        : "=r"(r[0]),"=r"(r[1]) : "r"(a));
}
__device__ __forceinline__ void ldsm2t(u32 a, u32* r){
    asm volatile("ldmatrix.sync.aligned.m8n8.x2.trans.shared.b16 {%0,%1}, [%2];"
        : "=r"(r[0]),"=r"(r[1]) : "r"(a));
}

// softmax over 22 nodes; lane i = row i; writes fp16 att row (stride 80B)
__device__ __forceinline__ void warp_softmax_h16(const float* __restrict__ ev, const float* __restrict__ adjs,
                                                 char* __restrict__ attb, int lane)
{
    if (lane < Nn) {
        int i = lane;
        float esrc = ev[i];
        float vals[Nn];
        float mx = -1e30f;
#pragma unroll
        for (int j = 0; j < Nn; j++) {
            if (adjs[i * Nn + j] != 0.0f) {
                float v = esrc + ev[Nn + j];
                v = (v > 0.0f) ? v : 0.2f * v;
                vals[j] = v;
                mx = fmaxf(mx, v);
            } else vals[j] = -1e30f;
        }
        float ssum = 0.0f;
#pragma unroll
        for (int j = 0; j < Nn; j++) {
            float e = (vals[j] > -1e29f) ? __expf(vals[j] - mx) : 0.0f;
            vals[j] = e; ssum += e;
        }
        float inv = 1.0f / ssum;
#pragma unroll
        for (int j = 0; j < Nn; j++) {
            __half hv = __float2half_rn(vals[j] * inv);
            *(u16*)(attb + i * 80 + j * 2) = *(u16*)&hv;
        }
    }
}

// stream one B chunk: 200 n-rows x 64 k fp16 (1600 x 16B ops)
__device__ __forceinline__ void issue_b(u32 dst, const __half* g, int tid, int rs)
{
#pragma unroll
    for (int q = 0; q < 4; q++) {
        int lin = tid + THREADS * q;
        if (lin < BROWS * 8) {
            int row = lin >> 3, piece = lin & 7;
            CPA16(dst + row * BSTR + piece * 16, g + row * rs + piece * 8);
        }
    }
}

// Streamed GEMM over nch k64-chunks. Chunks c0,c1 must be pre-issued (bufs 0,1).
// Chunk kc lives in buf kc%3. At kc issues stream-chunk kc+2 (own, or next gemm's
// first two). A plane: aoff0 for kc<3, aoff1 for kc>=3. wn==7 also accumulates the
// extra n8 tile (cols 192..199) into acce (e-columns at 192/193).
__device__ __forceinline__ void gemm_n(u32 sb, float acc[3][3][4], float acce[3][4],
                                       u32 aoff0, u32 aoff1,
                                       const __half* b0g, int rs,
                                       const __half* nextg, int nrs, int nch,
                                       int tid, int wm, int wn, int lane)
{
    const u32 laneA = (u32)((lane & 15) * ASTR + (lane >> 4) * 16);
    const u32 laneB = (u32)((lane & 7) * BSTR + ((lane >> 3) & 1) * 16);
    const u32 Bwarp = wn * 24 * BSTR + laneB;

    for (int kc = 0; kc < nch; kc++) {
        if (kc < nch - 1 || nextg) { CPW1(); } else { CPW0(); }
        __syncthreads();
        int sc = kc + 2;
        if (sc < nch) {
            issue_b(sb + OFF_B + (sc % 3) * BBUF, b0g + sc * 64, tid, rs);
            CPC();
        } else if (nextg && sc - nch < 2) {
            issue_b(sb + OFF_B + (sc % 3) * BBUF, nextg + (sc - nch) * 64, tid, nrs);
            CPC();
        }
        const u32 Ah = sb + (kc < 3 ? aoff0 + kc * 128 : aoff1 + (kc - 3) * 128)
                       + wm * 48 * ASTR + laneA;
        const u32 Bh = sb + OFF_B + (kc % 3) * BBUF + Bwarp;
#pragma unroll
        for (int s = 0; s < 4; s++) {
            u32 ah[3][4], bh[3][2];
#pragma unroll
            for (int mt = 0; mt < 3; mt++)
                ldsm4(Ah + mt * 16 * ASTR + s * 32, ah[mt]);
#pragma unroll
            for (int t = 0; t < 3; t++)
                ldsm2(Bh + t * 8 * BSTR + s * 32, bh[t]);
#pragma unroll
            for (int mt = 0; mt < 3; mt++)
#pragma unroll
                for (int t = 0; t < 3; t++)
                    mma_f16(acc[mt][t], ah[mt], bh[t][0], bh[t][1]);
            if (wn == 7) {
                u32 be[2];
                ldsm2(Bh + 3 * 8 * BSTR + s * 32, be);
#pragma unroll
                for (int mt = 0; mt < 3; mt++)
                    mma_f16(acce[mt], ah[mt], be[0], be[1]);
            }
        }
    }
}

// ================= prep: fp16 weights + e-rows =================
__global__ void k_prep(const float* __restrict__ W1, const float* __restrict__ W2,
                       const float* __restrict__ Wo, const float* __restrict__ a1,
                       const float* __restrict__ a2, const float* __restrict__ ao)
{
    int idx = blockIdx.x * blockDim.x + threadIdx.x;
    if (idx < 2 * 200 * 192) {
        int h = idx / (200 * 192);
        int rem = idx - h * 200 * 192;
        int n = rem / 192, k = rem % 192;
        const float* W = h ? W2 : W1;
        const float* a = h ? a2 : a1;
        float v;
        if (n < 192) v = W[k * 192 + n];
        else if (n < 194) {
            int sd = n - 192;
            float s = 0.0f;
            for (int m = 0; m < 192; m++) s += W[k * 192 + m] * a[sd * 192 + m];
            v = s;
        } else v = 0.0f;
        g_w12t[h * 200 * 192 + n * 192 + k] = __float2half_rn(v);
    } else if (idx < 2 * 200 * 192 + 200 * 384) {
        int j = idx - 2 * 200 * 192;
        int n = j / 384, k = j % 384;
        float v;
        if (n < 192) v = Wo[k * 192 + n];
        else if (n < 194) {
            int sd = n - 192;
            float s = 0.0f;
            for (int m = 0; m < 192; m++) s += Wo[k * 192 + m] * ao[sd * 192 + m];
            v = s;
        } else v = 0.0f;
        g_wot[n * 384 + k] = __float2half_rn(v);
    }
}

// ================= fused kernel =================
__global__ __launch_bounds__(THREADS, 1)
void k_fused(const float* __restrict__ x, const float* __restrict__ adj,
             float* __restrict__ out, int nbatch)
{
    extern __shared__ char smc[];
    float* smf = (float*)smc;
    const u32 sb = smem_u32(smc);
    const int tid = threadIdx.x, wid = tid >> 5, lane = tid & 31;
    const int l4 = lane >> 2, lq = lane & 3;
    const int wm = wid & 1, wn = wid >> 1;       // GEMM roles: 2M x 8N
    const int wb = wid >> 2, q = wid & 3;        // attention roles: 4 batches x 4 slices
    const int b0 = blockIdx.x * NB4;
    const int nb = min(NB4, nbatch - b0);
    const int nrows = nb * Nn;
    const long long row0 = (long long)b0 * Nn;

    float* adjs = smf + OFF_ADJ / 4;

    // prefetch GEMM1-h0 chunks 0,1
    issue_b(sb + OFF_B, g_w12t, tid, 192);
    CPC();
    issue_b(sb + OFF_B + BBUF, g_w12t + 64, tid, 192);
    CPC();

    for (int i = tid; i < Nn * Nn; i += THREADS) adjs[i] = adj[i];

    // zero: att pads, WHS rows 96..97, AH rows 88..97 (finite for ldsm2t over-reads)
    for (int i = tid; i < 2560; i += THREADS) ((u32*)(smc + OFF_ATT))[i] = 0;
    for (int i = tid; i < 200; i += THREADS)  ((u32*)(smc + OFF_WHS + 96 * ASTR))[i] = 0;
    for (int i = tid; i < 1000; i += THREADS) ((u32*)(smc + OFF_AH + 88 * ASTR))[i] = 0;

    // AX = fp16(x): 96 rows x 192 (pad rows zeroed) — written ONCE
    for (int idx = tid; idx < MR * 96; idx += THREADS) {
        int r = idx / 96, kp = idx % 96;
        float2 v = make_float2(0.f, 0.f);
        if (r < nrows) v = *(const float2*)(x + (row0 + r) * Fd + kp * 2);
        __half2 h2 = __float22half2_rn(v);
        *(u32*)(smc + OFF_AX + r * ASTR + kp * 4) = *(u32*)&h2;
    }

    // ===== two heads: GEMM1 + attention =====
    for (int h = 0; h < 2; h++) {
        float acc[3][3][4], acce[3][4];
#pragma unroll
        for (int mt = 0; mt < 3; mt++) {
#pragma unroll
            for (int nt = 0; nt < 3; nt++)
#pragma unroll
                for (int p = 0; p < 4; p++) acc[mt][nt][p] = 0.0f;
#pragma unroll
            for (int p = 0; p < 4; p++) acce[mt][p] = 0.0f;
        }

        gemm_n(sb, acc, acce, OFF_AX, OFF_AX, g_w12t + h * 200 * 192, 192,
               (h == 0) ? (g_w12t + 200 * 192) : g_wot, (h == 0) ? 192 : 384, 3,
               tid, wm, wn, lane);

        // epilogue: Wh -> WHS (fp16), e columns -> ev (warp-exclusive writes)
#pragma unroll
        for (int mt = 0; mt < 3; mt++)
#pragma unroll
            for (int nt = 0; nt < 3; nt++) {
                int r = wm * 48 + mt * 16 + l4, c = wn * 24 + nt * 8 + lq * 2;
                __half2 p0 = __floats2half2_rn(acc[mt][nt][0], acc[mt][nt][1]);
                __half2 p1 = __floats2half2_rn(acc[mt][nt][2], acc[mt][nt][3]);
                *(u32*)(smc + OFF_WHS + r * ASTR + c * 2)       = *(u32*)&p0;
                *(u32*)(smc + OFF_WHS + (r + 8) * ASTR + c * 2) = *(u32*)&p1;
            }
        if (wn == 7 && lq == 0) {
#pragma unroll
            for (int mt = 0; mt < 3; mt++) {
                int r = wm * 48 + mt * 16 + l4;
                if (r < NB4 * Nn) {
                    int bb = r / Nn, ii = r - bb * Nn;
                    float* evb = smf + OFF_WS / 4 + bb * 64;
                    evb[ii] = acce[mt][0]; evb[Nn + ii] = acce[mt][1];
                }
                int r2 = r + 8;
                if (r2 < NB4 * Nn) {
                    int bb = r2 / Nn, ii = r2 - bb * Nn;
                    float* evb = smf + OFF_WS / 4 + bb * 64;
                    evb[ii] = acce[mt][2]; evb[Nn + ii] = acce[mt][3];
                }
            }
        }
        __syncthreads();
        if (q == 0) warp_softmax_h16(smf + OFF_WS / 4 + wb * 64, adjs,
                                     smc + OFF_ATT + wb * 2560, lane);
        __syncthreads();

        // hc = elu(att @ Wh) via MMA; h0 -> AH, h1 -> WHS in place
        {
            const u32 attb = sb + OFF_ATT + wb * 2560;
            const u32 whb  = sb + OFF_WHS + (wb * Nn) * ASTR;
            const u32 dsto = (h == 0) ? OFF_AH : OFF_WHS;
            float aw[2][6][4];
#pragma unroll
            for (int mt = 0; mt < 2; mt++)
#pragma unroll
                for (int nt = 0; nt < 6; nt++)
#pragma unroll
                    for (int p = 0; p < 4; p++) aw[mt][nt][p] = 0.0f;

            u32 afr[2][2][4];
#pragma unroll
            for (int mt = 0; mt < 2; mt++)
#pragma unroll
                for (int ks = 0; ks < 2; ks++)
                    ldsm4(attb + (mt * 16 + (lane & 15)) * 80 + (lane >> 4) * 16 + ks * 32,
                          afr[mt][ks]);
#pragma unroll
            for (int nt = 0; nt < 6; nt++) {
                int n0 = q * 48 + nt * 8;
                u32 bfr[2][2];
#pragma unroll
                for (int ks = 0; ks < 2; ks++)
                    ldsm2t(whb + (ks * 16 + (lane & 15)) * ASTR + n0 * 2, bfr[ks]);
#pragma unroll
                for (int mt = 0; mt < 2; mt++)
#pragma unroll
                    for (int ks = 0; ks < 2; ks++)
                        mma_f16(aw[mt][nt], afr[mt][ks], bfr[ks][0], bfr[ks][1]);
            }
#pragma unroll
            for (int mt = 0; mt < 2; mt++)
#pragma unroll
                for (int nt = 0; nt < 6; nt++) {
                    int r0 = mt * 16 + l4, r1 = r0 + 8;
                    int c = q * 48 + nt * 8 + lq * 2;
                    if (r0 < Nn) {
                        __half2 p0 = __floats2half2_rn(elu1(aw[mt][nt][0]), elu1(aw[mt][nt][1]));
                        *(u32*)(smc + dsto + (wb * Nn + r0) * ASTR + c * 2) = *(u32*)&p0;
                    }
                    if (r1 < Nn) {
                        __half2 p1 = __floats2half2_rn(elu1(aw[mt][nt][2]), elu1(aw[mt][nt][3]));
                        *(u32*)(smc + dsto + (wb * Nn + r1) * ASTR + c * 2) = *(u32*)&p1;
                    }
                }
        }
        // next gemm's kc0 barrier publishes hc writes before A-reads
    }

    // ===== GEMM2: who = hcat @ Wo, K=384 in one pass (A: AH then WHS) =====
    float acc2[3][3][4], acc2e[3][4];
#pragma unroll
    for (int mt = 0; mt < 3; mt++) {
#pragma unroll
        for (int nt = 0; nt < 3; nt++)
#pragma unroll
            for (int p = 0; p < 4; p++) acc2[mt][nt][p] = 0.0f;
#pragma unroll
        for (int p = 0; p < 4; p++) acc2e[mt][p] = 0.0f;
    }
    gemm_n(sb, acc2, acc2e, OFF_AH, OFF_WHS, g_wot, 384,
           (const __half*)0, 0, 6, tid, wm, wn, lane);

    // epilogue: who -> AH (fp16), e_o -> ev. Safe without pre-barrier: kc5
    // stragglers read WHS/B only, never AH or ev.
#pragma unroll
    for (int mt = 0; mt < 3; mt++)
#pragma unroll
        for (int nt = 0; nt < 3; nt++) {
            int r = wm * 48 + mt * 16 + l4, c = wn * 24 + nt * 8 + lq * 2;
            __half2 p0 = __floats2half2_rn(acc2[mt][nt][0], acc2[mt][nt][1]);
            __half2 p1 = __floats2half2_rn(acc2[mt][nt][2], acc2[mt][nt][3]);
            *(u32*)(smc + OFF_AH + r * ASTR + c * 2)       = *(u32*)&p0;
            *(u32*)(smc + OFF_AH + (r + 8) * ASTR + c * 2) = *(u32*)&p1;
        }
    if (wn == 7 && lq == 0) {
#pragma unroll
        for (int mt = 0; mt < 3; mt++) {
            int r = wm * 48 + mt * 16 + l4;
            if (r < NB4 * Nn) {
                int bb = r / Nn, ii = r - bb * Nn;
                float* evb = smf + OFF_WS / 4 + bb * 64;
                evb[ii] = acc2e[mt][0]; evb[Nn + ii] = acc2e[mt][1];
            }
            int r2 = r + 8;
            if (r2 < NB4 * Nn) {
                int bb = r2 / Nn, ii = r2 - bb * Nn;
                float* evb = smf + OFF_WS / 4 + bb * 64;
                evb[ii] = acc2e[mt][2]; evb[Nn + ii] = acc2e[mt][3];
            }
        }
    }
    __syncthreads();
    if (q == 0) warp_softmax_h16(smf + OFF_WS / 4 + wb * 64, adjs,
                                 smc + OFF_ATT + wb * 2560, lane);
    __syncthreads();

    // ===== output: att_o @ who via MMA + elu + residual -> gmem =====
    {
        const u32 attb = sb + OFF_ATT + wb * 2560;
        const u32 whb  = sb + OFF_AH + (wb * Nn) * ASTR;
        float aw[2][6][4];
#pragma unroll
        for (int mt = 0; mt < 2; mt++)
#pragma unroll
            for (int nt = 0; nt < 6; nt++)
#pragma unroll
                for (int p = 0; p < 4; p++) aw[mt][nt][p] = 0.0f;

        u32 afr[2][2][4];
#pragma unroll
        for (int mt = 0; mt < 2; mt++)
#pragma unroll
            for (int ks = 0; ks < 2; ks++)
                ldsm4(attb + (mt * 16 + (lane & 15)) * 80 + (lane >> 4) * 16 + ks * 32,
                      afr[mt][ks]);
#pragma unroll
        for (int nt = 0; nt < 6; nt++) {
            int n0 = q * 48 + nt * 8;
            u32 bfr[2][2];
#pragma unroll
            for (int ks = 0; ks < 2; ks++)
                ldsm2t(whb + (ks * 16 + (lane & 15)) * ASTR + n0 * 2, bfr[ks]);
#pragma unroll
            for (int mt = 0; mt < 2; mt++)
#pragma unroll
                for (int ks = 0; ks < 2; ks++)
                    mma_f16(aw[mt][nt], afr[mt][ks], bfr[ks][0], bfr[ks][1]);
        }
        if (wb < nb) {
#pragma unroll
            for (int mt = 0; mt < 2; mt++)
#pragma unroll
                for (int nt = 0; nt < 6; nt++) {
                    int r0 = mt * 16 + l4, r1 = r0 + 8;
                    int c = q * 48 + nt * 8 + lq * 2;
                    if (r0 < Nn) {
                        long long gi = (row0 + wb * Nn + r0) * Fd + c;
                        float2 xr = *(const float2*)(x + gi);
                        float2 o;
                        o.x = elu1(aw[mt][nt][0]) + xr.x;
                        o.y = elu1(aw[mt][nt][1]) + xr.y;
                        *(float2*)(out + gi) = o;
                    }
                    if (r1 < Nn) {
                        long long gi = (row0 + wb * Nn + r1) * Fd + c;
                        float2 xr = *(const float2*)(x + gi);
                        float2 o;
                        o.x = elu1(aw[mt][nt][2]) + xr.x;
                        o.y = elu1(aw[mt][nt][3]) + xr.y;
                        *(float2*)(out + gi) = o;
                    }
                }
        }
    }
}

extern "C" void kernel_launch(void* const* d_in, const int* in_sizes, int n_in,
                              void* d_out, int out_size)
{
    const float* x   = (const float*)d_in[0];
    const float* adj = (const float*)d_in[1];
    const float* W1  = (const float*)d_in[2];
    const float* a1  = (const float*)d_in[3];
    const float* W2  = (const float*)d_in[4];
    const float* a2  = (const float*)d_in[5];
    const float* Wo  = (const float*)d_in[6];
    const float* ao  = (const float*)d_in[7];
    float* out = (float*)d_out;

    int nbatch = in_sizes[0] / (Nn * Fd);
    int ctas = (nbatch + NB4 - 1) / NB4;

    cudaFuncSetAttribute(k_fused, cudaFuncAttributeMaxDynamicSharedMemorySize, SMEM_TOTAL);

    int prep_elems = 2 * 200 * 192 + 200 * 384;
    k_prep<<<(prep_elems + 255) / 256, 256>>>(W1, W2, Wo, a1, a2, ao);
    k_fused<<<ctas, THREADS, SMEM_TOTAL>>>(x, adj, out, nbatch);
}

// round 17
// speedup vs baseline: 1.4934x; 1.0279x over previous
#include <cuda_runtime.h>
#include <cuda_fp16.h>

#define Nn 22
#define Fd 192
#define NB4 4
#define MR 96
#define THREADS 512

typedef unsigned int u32;
typedef unsigned short u16;

// ---- SMEM layout (bytes) ----
#define OFF_ADJ 0                 // 484 f
#define OFF_WS  1952              // 4 x 64 f ev (esrc[22], edst[22])
#define OFF_ATT 2976              // 4 x 32 rows x 80B fp16 att (zero padded)
#define OFF_AX  13216             // x fp16: 96 rows x 400B
#define ASTR    400
#define OFF_AH  51616             // hc0 / who fp16: 98 rows x 400B (rows 88..97 zeroed)
#define OFF_WHS 90816             // Wh / hc1 fp16: 98 rows x 400B (rows 96..97 zeroed)
#define OFF_B   130016            // 3-stage: 3 x (200 rows x 64 fp16, stride 144)
#define BSTR    144
#define BROWS   200
#define BBUF    28800
#define SMEM_TOTAL 216416

// ---- device-global fp16 weights with e-rows (sanctioned scratch) ----
// per head: 200 rows x 192 (rows 0..191 = W^T, 192/193 = W@a_src/dst, 194.. = 0)
static __device__ __half g_w12t[2*200*192];
// 200 rows x 384 (rows 0..191 = Wo^T, 192/193 = Wo@ao_src/dst, 194.. = 0)
static __device__ __half g_wot[200*384];

// ---- helpers ----
__device__ __forceinline__ u32 smem_u32(const void* p){
    u32 a;
    asm("{ .reg .u64 t; cvta.to.shared.u64 t, %1; cvt.u32.u64 %0, t; }" : "=r"(a) : "l"(p));
    return a;
}
__device__ __forceinline__ float elu1(float v){ return (v > 0.0f) ? v : (__expf(v) - 1.0f); }

#define CPA16(sa, g) asm volatile("cp.async.cg.shared.global [%0], [%1], 16;" :: "r"((u32)(sa)), "l"(g) : "memory")
#define CPC()  asm volatile("cp.async.commit_group;" ::: "memory")
#define CPW1() asm volatile("cp.async.wait_group 1;" ::: "memory")
#define CPW0() asm volatile("cp.async.wait_group 0;" ::: "memory")

__device__ __forceinline__ void mma_f16(float* c, const u32* a, u32 b0, u32 b1){
    asm volatile("mma.sync.aligned.m16n8k16.row.col.f32.f16.f16.f32 "
        "{%0,%1,%2,%3}, {%4,%5,%6,%7}, {%8,%9}, {%0,%1,%2,%3};"
        : "+f"(c[0]),"+f"(c[1]),"+f"(c[2]),"+f"(c[3])
        : "r"(a[0]),"r"(a[1]),"r"(a[2]),"r"(a[3]),"r"(b0),"r"(b1));
}
__device__ __forceinline__ void ldsm4(u32 a, u32* r){
    asm volatile("ldmatrix.sync.aligned.m8n8.x4.shared.b16 {%0,%1,%2,%3}, [%4];"
        : "=r"(r[0]),"=r"(r[1]),"=r"(r[2]),"=r"(r[3]) : "r"(a));
}
__device__ __forceinline__ void ldsm2t(u32 a, u32* r){
    asm volatile("ldmatrix.sync.aligned.m8n8.x2.trans.shared.b16 {%0,%1}, [%2];"
        : "=r"(r[0]),"=r"(r[1]) : "r"(a));
}

// softmax over 22 nodes; lane i = row i; writes fp16 att row (stride 80B)
__device__ __forceinline__ void warp_softmax_h16(const float* __restrict__ ev, const float* __restrict__ adjs,
                                                 char* __restrict__ attb, int lane)
{
    if (lane < Nn) {
        int i = lane;
        float esrc = ev[i];
        float vals[Nn];
        float mx = -1e30f;
#pragma unroll
        for (int j = 0; j < Nn; j++) {
            if (adjs[i * Nn + j] != 0.0f) {
                float v = esrc + ev[Nn + j];
                v = (v > 0.0f) ? v : 0.2f * v;
                vals[j] = v;
                mx = fmaxf(mx, v);
            } else vals[j] = -1e30f;
        }
        float ssum = 0.0f;
#pragma unroll
        for (int j = 0; j < Nn; j++) {
            float e = (vals[j] > -1e29f) ? __expf(vals[j] - mx) : 0.0f;
            vals[j] = e; ssum += e;
        }
        float inv = 1.0f / ssum;
#pragma unroll
        for (int j = 0; j < Nn; j++) {
            __half hv = __float2half_rn(vals[j] * inv);
            *(u16*)(attb + i * 80 + j * 2) = *(u16*)&hv;
        }
    }
}

// stream one B chunk: 200 n-rows x 64 k fp16 (1600 x 16B ops)
__device__ __forceinline__ void issue_b(u32 dst, const __half* g, int tid, int rs)
{
#pragma unroll
    for (int q = 0; q < 4; q++) {
        int lin = tid + THREADS * q;
        if (lin < BROWS * 8) {
            int row = lin >> 3, piece = lin & 7;
            CPA16(dst + row * BSTR + piece * 16, g + row * rs + piece * 8);
        }
    }
}

// Streamed GEMM over nch k64-chunks. Chunks c0,c1 pre-issued (bufs 0,1).
// Chunk kc in buf kc%3; at kc issues stream-chunk kc+2 (own or next gemm's).
// A plane: aoff0 for kc<3, aoff1 for kc>=3. B fragments via 2x ldsm4 covering
// 4 n8 tiles; 4th tile = e-columns for wn==7 (acce), unused otherwise.
__device__ __forceinline__ void gemm_n(u32 sb, float acc[3][3][4], float acce[3][4],
                                       u32 aoff0, u32 aoff1,
                                       const __half* b0g, int rs,
                                       const __half* nextg, int nrs, int nch,
                                       int tid, int wm, int wn, int lane)
{
    const u32 laneA = (u32)((lane & 15) * ASTR + (lane >> 4) * 16);
    const u32 laneB4 = (u32)((lane & 7) * BSTR + ((lane >> 3) & 1) * 16 + (lane >> 4) * (8 * BSTR));
    const u32 Bwarp = wn * 24 * BSTR + laneB4;

    for (int kc = 0; kc < nch; kc++) {
        if (kc < nch - 1 || nextg) { CPW1(); } else { CPW0(); }
        __syncthreads();
        int sc = kc + 2;
        if (sc < nch) {
            issue_b(sb + OFF_B + (sc % 3) * BBUF, b0g + sc * 64, tid, rs);
            CPC();
        } else if (nextg && sc - nch < 2) {
            issue_b(sb + OFF_B + (sc % 3) * BBUF, nextg + (sc - nch) * 64, tid, nrs);
            CPC();
        }
        const u32 Ah = sb + (kc < 3 ? aoff0 + kc * 128 : aoff1 + (kc - 3) * 128)
                       + wm * 48 * ASTR + laneA;
        const u32 Bh = sb + OFF_B + (kc % 3) * BBUF + Bwarp;
#pragma unroll
        for (int s = 0; s < 4; s++) {
            u32 ah[3][4], bb0[4], bb1[4];
#pragma unroll
            for (int mt = 0; mt < 3; mt++)
                ldsm4(Ah + mt * 16 * ASTR + s * 32, ah[mt]);
            ldsm4(Bh + s * 32, bb0);                    // tiles 0,1
            ldsm4(Bh + 16 * BSTR + s * 32, bb1);        // tiles 2,3(e)
#pragma unroll
            for (int mt = 0; mt < 3; mt++) {
                mma_f16(acc[mt][0], ah[mt], bb0[0], bb0[1]);
                mma_f16(acc[mt][1], ah[mt], bb0[2], bb0[3]);
                mma_f16(acc[mt][2], ah[mt], bb1[0], bb1[1]);
            }
            if (wn == 7) {
#pragma unroll
                for (int mt = 0; mt < 3; mt++)
                    mma_f16(acce[mt], ah[mt], bb1[2], bb1[3]);
            }
        }
    }
}

// ================= prep: fp16 weights + e-rows =================
__global__ void k_prep(const float* __restrict__ W1, const float* __restrict__ W2,
                       const float* __restrict__ Wo, const float* __restrict__ a1,
                       const float* __restrict__ a2, const float* __restrict__ ao)
{
    int idx = blockIdx.x * blockDim.x + threadIdx.x;
    if (idx < 2 * 200 * 192) {
        int h = idx / (200 * 192);
        int rem = idx - h * 200 * 192;
        int n = rem / 192, k = rem % 192;
        const float* W = h ? W2 : W1;
        const float* a = h ? a2 : a1;
        float v;
        if (n < 192) v = W[k * 192 + n];
        else if (n < 194) {
            int sd = n - 192;
            float s = 0.0f;
            for (int m = 0; m < 192; m++) s += W[k * 192 + m] * a[sd * 192 + m];
            v = s;
        } else v = 0.0f;
        g_w12t[h * 200 * 192 + n * 192 + k] = __float2half_rn(v);
    } else if (idx < 2 * 200 * 192 + 200 * 384) {
        int j = idx - 2 * 200 * 192;
        int n = j / 384, k = j % 384;
        float v;
        if (n < 192) v = Wo[k * 192 + n];
        else if (n < 194) {
            int sd = n - 192;
            float s = 0.0f;
            for (int m = 0; m < 192; m++) s += Wo[k * 192 + m] * ao[sd * 192 + m];
            v = s;
        } else v = 0.0f;
        g_wot[n * 384 + k] = __float2half_rn(v);
    }
}

// ================= fused kernel =================
__global__ __launch_bounds__(THREADS, 1)
void k_fused(const float* __restrict__ x, const float* __restrict__ adj,
             float* __restrict__ out, int nbatch)
{
    extern __shared__ char smc[];
    float* smf = (float*)smc;
    const u32 sb = smem_u32(smc);
    const int tid = threadIdx.x, wid = tid >> 5, lane = tid & 31;
    const int l4 = lane >> 2, lq = lane & 3;
    const int wm = wid & 1, wn = wid >> 1;       // GEMM roles: 2M x 8N
    const int wb = wid >> 2, q = wid & 3;        // attention roles: 4 batches x 4 slices
    const int b0 = blockIdx.x * NB4;
    const int nb = min(NB4, nbatch - b0);
    const int nrows = nb * Nn;
    const long long row0 = (long long)b0 * Nn;

    float* adjs = smf + OFF_ADJ / 4;

    // prefetch GEMM1-h0 chunks 0,1
    issue_b(sb + OFF_B, g_w12t, tid, 192);
    CPC();
    issue_b(sb + OFF_B + BBUF, g_w12t + 64, tid, 192);
    CPC();

    for (int i = tid; i < Nn * Nn; i += THREADS) adjs[i] = adj[i];

    // zero: att pads, WHS rows 96..97, AH rows 88..97 (finite for ldsm2t over-reads)
    for (int i = tid; i < 2560; i += THREADS) ((u32*)(smc + OFF_ATT))[i] = 0;
    for (int i = tid; i < 200; i += THREADS)  ((u32*)(smc + OFF_WHS + 96 * ASTR))[i] = 0;
    for (int i = tid; i < 1000; i += THREADS) ((u32*)(smc + OFF_AH + 88 * ASTR))[i] = 0;

    // AX = fp16(x): 96 rows x 192 (pad rows zeroed) — written ONCE
    for (int idx = tid; idx < MR * 96; idx += THREADS) {
        int r = idx / 96, kp = idx % 96;
        float2 v = make_float2(0.f, 0.f);
        if (r < nrows) v = *(const float2*)(x + (row0 + r) * Fd + kp * 2);
        __half2 h2 = __float22half2_rn(v);
        *(u32*)(smc + OFF_AX + r * ASTR + kp * 4) = *(u32*)&h2;
    }

    // ===== two heads: GEMM1 + attention =====
    for (int h = 0; h < 2; h++) {
        float acc[3][3][4], acce[3][4];
#pragma unroll
        for (int mt = 0; mt < 3; mt++) {
#pragma unroll
            for (int nt = 0; nt < 3; nt++)
#pragma unroll
                for (int p = 0; p < 4; p++) acc[mt][nt][p] = 0.0f;
#pragma unroll
            for (int p = 0; p < 4; p++) acce[mt][p] = 0.0f;
        }

        gemm_n(sb, acc, acce, OFF_AX, OFF_AX, g_w12t + h * 200 * 192, 192,
               (h == 0) ? (g_w12t + 200 * 192) : g_wot, (h == 0) ? 192 : 384, 3,
               tid, wm, wn, lane);

        // epilogue: Wh -> WHS (fp16), e columns -> ev (warp-exclusive writes)
#pragma unroll
        for (int mt = 0; mt < 3; mt++)
#pragma unroll
            for (int nt = 0; nt < 3; nt++) {
                int r = wm * 48 + mt * 16 + l4, c = wn * 24 + nt * 8 + lq * 2;
                __half2 p0 = __floats2half2_rn(acc[mt][nt][0], acc[mt][nt][1]);
                __half2 p1 = __floats2half2_rn(acc[mt][nt][2], acc[mt][nt][3]);
                *(u32*)(smc + OFF_WHS + r * ASTR + c * 2)       = *(u32*)&p0;
                *(u32*)(smc + OFF_WHS + (r + 8) * ASTR + c * 2) = *(u32*)&p1;
            }
        if (wn == 7 && lq == 0) {
#pragma unroll
            for (int mt = 0; mt < 3; mt++) {
                int r = wm * 48 + mt * 16 + l4;
                if (r < NB4 * Nn) {
                    int bb = r / Nn, ii = r - bb * Nn;
                    float* evb = smf + OFF_WS / 4 + bb * 64;
                    evb[ii] = acce[mt][0]; evb[Nn + ii] = acce[mt][1];
                }
                int r2 = r + 8;
                if (r2 < NB4 * Nn) {
                    int bb = r2 / Nn, ii = r2 - bb * Nn;
                    float* evb = smf + OFF_WS / 4 + bb * 64;
                    evb[ii] = acce[mt][2]; evb[Nn + ii] = acce[mt][3];
                }
            }
        }
        __syncthreads();
        // ALL warps compute softmax for their batch (identical redundant writes);
        // each warp then reads its OWN writes -> no barrier needed after.
        warp_softmax_h16(smf + OFF_WS / 4 + wb * 64, adjs,
                         smc + OFF_ATT + wb * 2560, lane);

        // hc = elu(att @ Wh) via MMA; h0 -> AH, h1 -> WHS in place
        {
            const u32 attb = sb + OFF_ATT + wb * 2560;
            const u32 whb  = sb + OFF_WHS + (wb * Nn) * ASTR;
            const u32 dsto = (h == 0) ? OFF_AH : OFF_WHS;
            float aw[2][6][4];
#pragma unroll
            for (int mt = 0; mt < 2; mt++)
#pragma unroll
                for (int nt = 0; nt < 6; nt++)
#pragma unroll
                    for (int p = 0; p < 4; p++) aw[mt][nt][p] = 0.0f;

            u32 afr[2][2][4];
#pragma unroll
            for (int mt = 0; mt < 2; mt++)
#pragma unroll
                for (int ks = 0; ks < 2; ks++)
                    ldsm4(attb + (mt * 16 + (lane & 15)) * 80 + (lane >> 4) * 16 + ks * 32,
                          afr[mt][ks]);
#pragma unroll
            for (int nt = 0; nt < 6; nt++) {
                int n0 = q * 48 + nt * 8;
                u32 bfr[2][2];
#pragma unroll
                for (int ks = 0; ks < 2; ks++)
                    ldsm2t(whb + (ks * 16 + (lane & 15)) * ASTR + n0 * 2, bfr[ks]);
#pragma unroll
                for (int mt = 0; mt < 2; mt++)
#pragma unroll
                    for (int ks = 0; ks < 2; ks++)
                        mma_f16(aw[mt][nt], afr[mt][ks], bfr[ks][0], bfr[ks][1]);
            }
#pragma unroll
            for (int mt = 0; mt < 2; mt++)
#pragma unroll
                for (int nt = 0; nt < 6; nt++) {
                    int r0 = mt * 16 + l4, r1 = r0 + 8;
                    int c = q * 48 + nt * 8 + lq * 2;
                    if (r0 < Nn) {
                        __half2 p0 = __floats2half2_rn(elu1(aw[mt][nt][0]), elu1(aw[mt][nt][1]));
                        *(u32*)(smc + dsto + (wb * Nn + r0) * ASTR + c * 2) = *(u32*)&p0;
                    }
                    if (r1 < Nn) {
                        __half2 p1 = __floats2half2_rn(elu1(aw[mt][nt][2]), elu1(aw[mt][nt][3]));
                        *(u32*)(smc + dsto + (wb * Nn + r1) * ASTR + c * 2) = *(u32*)&p1;
                    }
                }
        }
        // next gemm's kc0 barrier publishes hc writes before A-reads
    }

    // ===== GEMM2: who = hcat @ Wo, K=384 in one pass (A: AH then WHS) =====
    float acc2[3][3][4], acc2e[3][4];
#pragma unroll
    for (int mt = 0; mt < 3; mt++) {
#pragma unroll
        for (int nt = 0; nt < 3; nt++)
#pragma unroll
            for (int p = 0; p < 4; p++) acc2[mt][nt][p] = 0.0f;
#pragma unroll
        for (int p = 0; p < 4; p++) acc2e[mt][p] = 0.0f;
    }
    gemm_n(sb, acc2, acc2e, OFF_AH, OFF_WHS, g_wot, 384,
           (const __half*)0, 0, 6, tid, wm, wn, lane);

    // epilogue: who -> AH (fp16), e_o -> ev. Safe without pre-barrier: kc5
    // stragglers read WHS/B only, never AH or ev.
#pragma unroll
    for (int mt = 0; mt < 3; mt++)
#pragma unroll
        for (int nt = 0; nt < 3; nt++) {
            int r = wm * 48 + mt * 16 + l4, c = wn * 24 + nt * 8 + lq * 2;
            __half2 p0 = __floats2half2_rn(acc2[mt][nt][0], acc2[mt][nt][1]);
            __half2 p1 = __floats2half2_rn(acc2[mt][nt][2], acc2[mt][nt][3]);
            *(u32*)(smc + OFF_AH + r * ASTR + c * 2)       = *(u32*)&p0;
            *(u32*)(smc + OFF_AH + (r + 8) * ASTR + c * 2) = *(u32*)&p1;
        }
    if (wn == 7 && lq == 0) {
#pragma unroll
        for (int mt = 0; mt < 3; mt++) {
            int r = wm * 48 + mt * 16 + l4;
            if (r < NB4 * Nn) {
                int bb = r / Nn, ii = r - bb * Nn;
                float* evb = smf + OFF_WS / 4 + bb * 64;
                evb[ii] = acc2e[mt][0]; evb[Nn + ii] = acc2e[mt][1];
            }
            int r2 = r + 8;
            if (r2 < NB4 * Nn) {
                int bb = r2 / Nn, ii = r2 - bb * Nn;
                float* evb = smf + OFF_WS / 4 + bb * 64;
                evb[ii] = acc2e[mt][2]; evb[Nn + ii] = acc2e[mt][3];
            }
        }
    }
    __syncthreads();
    warp_softmax_h16(smf + OFF_WS / 4 + wb * 64, adjs,
                     smc + OFF_ATT + wb * 2560, lane);

    // ===== output: att_o @ who via MMA + elu + residual -> gmem =====
    {
        const u32 attb = sb + OFF_ATT + wb * 2560;
        const u32 whb  = sb + OFF_AH + (wb * Nn) * ASTR;
        float aw[2][6][4];
#pragma unroll
        for (int mt = 0; mt < 2; mt++)
#pragma unroll
            for (int nt = 0; nt < 6; nt++)
#pragma unroll
                for (int p = 0; p < 4; p++) aw[mt][nt][p] = 0.0f;

        u32 afr[2][2][4];
#pragma unroll
        for (int mt = 0; mt < 2; mt++)
#pragma unroll
            for (int ks = 0; ks < 2; ks++)
                ldsm4(attb + (mt * 16 + (lane & 15)) * 80 + (lane >> 4) * 16 + ks * 32,
                      afr[mt][ks]);
#pragma unroll
        for (int nt = 0; nt < 6; nt++) {
            int n0 = q * 48 + nt * 8;
            u32 bfr[2][2];
#pragma unroll
            for (int ks = 0; ks < 2; ks++)
                ldsm2t(whb + (ks * 16 + (lane & 15)) * ASTR + n0 * 2, bfr[ks]);
#pragma unroll
            for (int mt = 0; mt < 2; mt++)
#pragma unroll
                for (int ks = 0; ks < 2; ks++)
                    mma_f16(aw[mt][nt], afr[mt][ks], bfr[ks][0], bfr[ks][1]);
        }
        if (wb < nb) {
#pragma unroll
            for (int mt = 0; mt < 2; mt++)
#pragma unroll
                for (int nt = 0; nt < 6; nt++) {
                    int r0 = mt * 16 + l4, r1 = r0 + 8;
                    int c = q * 48 + nt * 8 + lq * 2;
                    if (r0 < Nn) {
                        long long gi = (row0 + wb * Nn + r0) * Fd + c;
                        float2 xr = *(const float2*)(x + gi);
                        float2 o;
                        o.x = elu1(aw[mt][nt][0]) + xr.x;
                        o.y = elu1(aw[mt][nt][1]) + xr.y;
                        *(float2*)(out + gi) = o;
                    }
                    if (r1 < Nn) {
                        long long gi = (row0 + wb * Nn + r1) * Fd + c;
                        float2 xr = *(const float2*)(x + gi);
                        float2 o;
                        o.x = elu1(aw[mt][nt][2]) + xr.x;
                        o.y = elu1(aw[mt][nt][3]) + xr.y;
                        *(float2*)(out + gi) = o;
                    }
                }
        }
    }
}

extern "C" void kernel_launch(void* const* d_in, const int* in_sizes, int n_in,
                              void* d_out, int out_size)
{
    const float* x   = (const float*)d_in[0];
    const float* adj = (const float*)d_in[1];
    const float* W1  = (const float*)d_in[2];
    const float* a1  = (const float*)d_in[3];
    const float* W2  = (const float*)d_in[4];
    const float* a2  = (const float*)d_in[5];
    const float* Wo  = (const float*)d_in[6];
    const float* ao  = (const float*)d_in[7];
    float* out = (float*)d_out;

    int nbatch = in_sizes[0] / (Nn * Fd);
    int ctas = (nbatch + NB4 - 1) / NB4;

    cudaFuncSetAttribute(k_fused, cudaFuncAttributeMaxDynamicSharedMemorySize, SMEM_TOTAL);

    int prep_elems = 2 * 200 * 192 + 200 * 384;
    k_prep<<<(prep_elems + 255) / 256, 256>>>(W1, W2, Wo, a1, a2, ao);
    k_fused<<<ctas, THREADS, SMEM_TOTAL>>>(x, adj, out, nbatch);
}